// round 16
// baseline (speedup 1.0000x reference)
#include <cuda_runtime.h>
#include <math.h>

#define N_NODESC 20000
#define N_EDGESC 120000
#define HY_STRIDE 44

// ---- static device scratch (zero-initialized at module load) ----
__device__ int   g_deg[N_NODESC];     // zero invariant restored by k_scatter each run
__device__ int   g_off[N_NODESC + 1];
__device__ int   g_cursor[N_NODESC];
__device__ int2  g_edge[N_EDGESC];               // sorted (src,dst)
__device__ float g_MW[16 * 384];                 // MW[p][t], t=j*24+u (computed in k_hist blk 0)
__device__ float g_R[(size_t)N_NODESC * 384];    // R[n][j*24+u]
__device__ float g_hy[(size_t)N_EDGESC * HY_STRIDE + 16]; // per SORTED slot: hv'[16], y[24], expv

#define C_EMB   8.4335730690754870f
#define C_V     0.05103103630798287f
#define C_LOGIT 0.003189439769248930f

__device__ __forceinline__ float susf(float v) {
    return (v > 0.f) ? __expf(-__fdividef(1.f, v)) : 0.f;
}
__device__ __forceinline__ float siluf(float z) {
    return __fdividef(z, 1.f + __expf(-z));
}

// ---------------- hist (+ block 0 computes MW once) ----------------
__global__ void k_hist(const int* __restrict__ dst, const float* __restrict__ Wq,
                       const float* __restrict__ Wdot, const float* __restrict__ Wk2) {
    int i = blockIdx.x * 384 + threadIdx.x;
    if (i < N_EDGESC) atomicAdd(&g_deg[dst[i]], 1);

    if (blockIdx.x == 0) {
        __shared__ float sM[16][17];
        int t = threadIdx.x;  // 0..383
        if (t < 256) {
            int p = t >> 4, w = t & 15;
            float a = 0.f;
            #pragma unroll
            for (int r = 0; r < 16; r++) a += __ldg(&Wq[p * 16 + r]) * __ldg(&Wdot[r * 16 + w]);
            sM[p][w] = a * 0.25f * C_LOGIT;
        }
        __syncthreads();
        int j = t / 24, u = t - j * 24;
        float wk[16];
        #pragma unroll
        for (int w = 0; w < 16; w++) wk[w] = __ldg(&Wk2[j * 384 + u * 16 + w]);
        #pragma unroll
        for (int p = 0; p < 16; p++) {
            float a = 0.f;
            #pragma unroll
            for (int w = 0; w < 16; w++) a += sM[p][w] * wk[w];
            g_MW[p * 384 + t] = a;
        }
    }
}

__global__ void k_scan() {
    __shared__ int s[1024];
    int tid = threadIdx.x;
    const int CH = (N_NODESC + 1023) / 1024;  // 20
    int base = tid * CH;
    int sum = 0;
    #pragma unroll
    for (int c = 0; c < CH; c++) {
        int idx = base + c;
        if (idx < N_NODESC) sum += g_deg[idx];
    }
    s[tid] = sum;
    __syncthreads();
    for (int d = 1; d < 1024; d <<= 1) {
        int v = (tid >= d) ? s[tid - d] : 0;
        __syncthreads();
        s[tid] += v;
        __syncthreads();
    }
    int run = s[tid] - sum;
    for (int c = 0; c < CH; c++) {
        int idx = base + c;
        if (idx < N_NODESC) {
            g_off[idx] = run;
            g_cursor[idx] = run;
            run += g_deg[idx];
        }
    }
    if (tid == 1023) g_off[N_NODESC] = s[1023];
}

// scatter + re-zero g_deg (restores zero invariant for the next graph replay)
__global__ void k_scatter(const int* __restrict__ src, const int* __restrict__ dst) {
    int i = blockIdx.x * blockDim.x + threadIdx.x;
    if (i < N_EDGESC) {
        int d = dst[i];
        int p = atomicAdd(&g_cursor[d], 1);
        g_edge[p] = make_int2(src[i], d);
        if (i < N_NODESC) g_deg[i] = 0;
    }
}

// ---------------- R GEMM: R[n][t] = sum_p x0[n][p]*MW[p][t] ----------------
#define RT_NODES 25
__global__ void k_R(const float* __restrict__ x) {
    __shared__ float sq[RT_NODES * 16];
    int t = threadIdx.x;  // 0..383

    float wr[16];
    #pragma unroll
    for (int p = 0; p < 16; p++) wr[p] = g_MW[p * 384 + t];   // coalesced, L2-hot

    int nb = blockIdx.x * RT_NODES;
    for (int i = t; i < RT_NODES * 16; i += 384) {
        int n = i >> 4, c = i & 15;
        sq[i] = x[(size_t)(nb + n) * 40 + c];
    }
    __syncthreads();

    float* Rp = g_R + (size_t)nb * 384 + t;
    #pragma unroll 5
    for (int n0 = 0; n0 < RT_NODES; n0++) {
        const float4* q4 = (const float4*)(sq + n0 * 16);
        float4 qa = q4[0], qb = q4[1], qc = q4[2], qd = q4[3];
        float s0 = wr[0] * qa.x;  float s1 = wr[1] * qa.y;
        float s2 = wr[2] * qa.z;  float s3 = wr[3] * qa.w;
        s0 += wr[4] * qb.x;  s1 += wr[5] * qb.y;
        s2 += wr[6] * qb.z;  s3 += wr[7] * qb.w;
        s0 += wr[8] * qc.x;  s1 += wr[9] * qc.y;
        s2 += wr[10] * qc.z; s3 += wr[11] * qc.w;
        s0 += wr[12] * qd.x; s1 += wr[13] * qd.y;
        s2 += wr[14] * qd.z; s3 += wr[15] * qd.w;
        Rp[(size_t)n0 * 384] = (s0 + s1) + (s2 + s3);
    }
}

// ---------------- pass A: register-dieted, __launch_bounds__(256,4) ----------------
__global__ void __launch_bounds__(256, 4)
k_passA(const float* __restrict__ x, const float* __restrict__ pos,
        const float* __restrict__ Wk1, const float* __restrict__ Wv1) {
    __shared__ float s_wkv[320];
    {
        int tt = threadIdx.x;
        if (tt < 160) { s_wkv[tt] = __ldg(&Wk1[tt]); s_wkv[160 + tt] = __ldg(&Wv1[tt]); }
    }
    __syncthreads();

    int i = blockIdx.x * blockDim.x + threadIdx.x;
    if (i >= N_EDGESC) return;
    int2 sd = g_edge[i];
    int s = sd.x, d = sd.y;
    float* row = g_hy + (size_t)i * HY_STRIDE;

    float ev0 = pos[s * 3 + 0] - pos[d * 3 + 0];
    float ev1 = pos[s * 3 + 1] - pos[d * 3 + 1];
    float ev2 = pos[s * 3 + 2] - pos[d * 3 + 2];
    float elen = sqrtf(ev0 * ev0 + ev1 * ev1 + ev2 * ev2 + 1e-12f);

    float wcut = susf(10.f * (1.f - elen * 0.25f));
    if (!(wcut > 0.f)) {
        float4 z4 = make_float4(0.f, 0.f, 0.f, 0.f);
        ((float4*)row)[0] = z4; ((float4*)row)[1] = z4;
        ((float4*)row)[2] = z4; ((float4*)row)[3] = z4;
        ((float4*)row)[10] = z4;
        return;
    }

    float tt = elen * 2.75f;
    int b0 = (int)tt;
    float d0 = tt - (float)b0;
    float g0 = (b0 >= 1 && b0 <= 10) ? (C_EMB * susf(d0 + 1.f) * susf(1.f - d0)) : 0.f;
    float g1 = (b0 >= 0 && b0 <= 9)  ? (C_EMB * susf(d0) * susf(2.f - d0)) : 0.f;
    int r0 = b0 - 1; if (r0 < 0) r0 = 0; if (r0 > 9) r0 = 9;
    int r1 = b0;     if (r1 < 0) r1 = 0; if (r1 > 9) r1 = 9;

    const float4* xp4 = (const float4*)(x + (size_t)s * 40);
    float y[24];
    float rinv = __frcp_rn(elen);

    {
        float4 a0 = __ldg(&xp4[0]), a1 = __ldg(&xp4[1]);
        float4 a2 = __ldg(&xp4[2]), a3 = __ldg(&xp4[3]);
        y[0] = a0.x;  y[1] = a0.y;  y[2] = a0.z;  y[3] = a0.w;
        y[4] = a1.x;  y[5] = a1.y;  y[6] = a1.z;  y[7] = a1.w;
        y[8] = a2.x;  y[9] = a2.y;  y[10] = a2.z; y[11] = a2.w;
        y[12] = a3.x; y[13] = a3.y; y[14] = a3.z; y[15] = a3.w;
    }
    {
        float4 b0v = __ldg(&xp4[4]);
        float4 b1v = __ldg(&xp4[5]);
        float4 b2v = __ldg(&xp4[6]);
        y[16] = (b0v.x * ev0 + b0v.y * ev1 + b0v.z * ev2) * rinv;
        y[17] = (b0v.w * ev0 + b1v.x * ev1 + b1v.y * ev2) * rinv;
        y[18] = (b1v.z * ev0 + b1v.w * ev1 + b2v.x * ev2) * rinv;
        y[19] = (b2v.y * ev0 + b2v.z * ev1 + b2v.w * ev2) * rinv;
    }
    {
        float4 b3v = __ldg(&xp4[7]);
        float4 b4v = __ldg(&xp4[8]);
        float4 b5v = __ldg(&xp4[9]);
        y[20] = (b3v.x * ev0 + b3v.y * ev1 + b3v.z * ev2) * rinv;
        y[21] = (b3v.w * ev0 + b4v.x * ev1 + b4v.y * ev2) * rinv;
        y[22] = (b4v.z * ev0 + b4v.w * ev1 + b5v.x * ev2) * rinv;
        y[23] = (b5v.y * ev0 + b5v.z * ev1 + b5v.w * ev2) * rinv;
    }

    float lg = 0.f;
    const float4* Rp = (const float4*)(g_R + (size_t)d * 384);
    #pragma unroll
    for (int j = 0; j < 16; j++) {
        float zk = g0 * s_wkv[r0 * 16 + j] + g1 * s_wkv[r1 * 16 + j];
        float hk = siluf(zk);
        float Sj = 0.f;
        #pragma unroll
        for (int q4 = 0; q4 < 6; q4++) {
            float4 r4 = __ldg(&Rp[j * 6 + q4]);
            Sj += r4.x * y[q4 * 4 + 0] + r4.y * y[q4 * 4 + 1]
                + r4.z * y[q4 * 4 + 2] + r4.w * y[q4 * 4 + 3];
        }
        lg += hk * Sj;
    }
    float expv = wcut * __expf(lg);
    float sev = sqrtf(expv);

    #pragma unroll
    for (int j4 = 0; j4 < 4; j4++) {
        float h0 = sev * siluf(g0 * s_wkv[160 + r0 * 16 + j4 * 4 + 0] + g1 * s_wkv[160 + r1 * 16 + j4 * 4 + 0]);
        float h1 = sev * siluf(g0 * s_wkv[160 + r0 * 16 + j4 * 4 + 1] + g1 * s_wkv[160 + r1 * 16 + j4 * 4 + 1]);
        float h2 = sev * siluf(g0 * s_wkv[160 + r0 * 16 + j4 * 4 + 2] + g1 * s_wkv[160 + r1 * 16 + j4 * 4 + 2]);
        float h3 = sev * siluf(g0 * s_wkv[160 + r0 * 16 + j4 * 4 + 3] + g1 * s_wkv[160 + r1 * 16 + j4 * 4 + 3]);
        ((float4*)row)[j4] = make_float4(h0, h1, h2, h3);
    }
    #pragma unroll
    for (int q4 = 0; q4 < 6; q4++)
        ((float4*)(row + 16))[q4] = make_float4(y[q4 * 4 + 0], y[q4 * 4 + 1],
                                                y[q4 * 4 + 2], y[q4 * 4 + 3]);
    ((float4*)row)[10] = make_float4(expv, 0.f, 0.f, 0.f);
}

// ---------------- fused pass B + output GEMM (phase 2 float4, conflict-free) ----------------
#define BN 28
__global__ void __launch_bounds__(448)
k_passBout(const float* __restrict__ Wv2, float* __restrict__ out) {
    __shared__ __align__(16) float sT[BN][384];   // 43,008 B, rows 16B-aligned
    __shared__ __align__(16) float sWc[32][36];   // [col][kk], stride 36

    int t = threadIdx.x;
    int l = t & 31, w = t >> 5;       // warp 0..13
    int base = blockIdx.x * BN;
    int par = l >> 4;
    int jj = l & 15;

    // ---- phase 1: passB (warp per node, 2 nodes/warp) ----
    #pragma unroll
    for (int q = 0; q < 2; q++) {
        int n = base + w * 2 + q;
        float acc[12];
        #pragma unroll
        for (int k = 0; k < 12; k++) acc[k] = 0.f;
        float z = 0.f;

        if (n < N_NODESC) {
            int beg = g_off[n], end = g_off[n + 1];
            if (beg < end) {
                const float* row = g_hy + (size_t)beg * HY_STRIDE;
                float A = row[l];
                float B = (l < 16) ? row[32 + l] : 0.f;
                for (int i = beg; i < end; i++) {
                    float A2 = 0.f, B2 = 0.f;
                    if (i + 1 < end) {
                        const float* row2 = g_hy + (size_t)(i + 1) * HY_STRIDE;
                        A2 = row2[l];
                        B2 = (l < 16) ? row2[32 + l] : 0.f;
                    }
                    z += __shfl_sync(0xffffffffu, B, 8);
                    float hval = __shfl_sync(0xffffffffu, A, jj);
                    #pragma unroll
                    for (int k = 0; k < 8; k++) {
                        float yv = __shfl_sync(0xffffffffu, A, 16 + par + 2 * k);
                        acc[k] += hval * yv;
                    }
                    #pragma unroll
                    for (int k = 8; k < 12; k++) {
                        float yv = __shfl_sync(0xffffffffu, B, par + 2 * k - 16);
                        acc[k] += hval * yv;
                    }
                    A = A2; B = B2;
                }
            }
        }
        if (z == 0.f) z = 1.f;
        float sc = rsqrtf(z);
        #pragma unroll
        for (int k = 0; k < 12; k++) sT[w * 2 + q][l + 32 * k] = acc[k] * sc;
    }
    __syncthreads();

    // ---- phase 2: GEMM out = C_V * sT @ W', float4 LDS, conflict-free staging ----
    float acc0 = 0.f, acc1 = 0.f;
    const float* r0 = sT[w * 2];
    const float* r1 = sT[w * 2 + 1];
    for (int kc = 0; kc < 12; kc++) {
        // staging: col = i>>5 (fixed per warp), kk = i&31 (consecutive) -> conflict-free stores
        for (int i = t; i < 1024; i += 448) {
            int col = i >> 5, kk = i & 31;
            int k = kc * 32 + kk;
            sWc[col][kk] = __ldg(&Wv2[(k & 15) * 768 + (k >> 4) * 32 + col]);
        }
        __syncthreads();
        const float4* w4 = (const float4*)sWc[l];
        #pragma unroll
        for (int kk4 = 0; kk4 < 8; kk4++) {
            float4 wv = w4[kk4];
            float4 t0 = *(const float4*)(r0 + kc * 32 + kk4 * 4);   // warp-broadcast
            float4 t1 = *(const float4*)(r1 + kc * 32 + kk4 * 4);
            acc0 += wv.x * t0.x + wv.y * t0.y + wv.z * t0.z + wv.w * t0.w;
            acc1 += wv.x * t1.x + wv.y * t1.y + wv.z * t1.z + wv.w * t1.w;
        }
        __syncthreads();
    }
    int n0 = base + w * 2, n1 = n0 + 1;
    if (n0 < N_NODESC) out[n0 * 32 + l] = acc0 * C_V;
    if (n1 < N_NODESC) out[n1 * 32 + l] = acc1 * C_V;
}

// ---------------- launch: single stream, 6 kernels ----------------
extern "C" void kernel_launch(void* const* d_in, const int* in_sizes, int n_in,
                              void* d_out, int out_size) {
    (void)in_sizes; (void)n_in; (void)out_size;
    const float* x    = (const float*)d_in[0];
    const float* pos  = (const float*)d_in[1];
    const float* Wq   = (const float*)d_in[2];
    const float* Wk1  = (const float*)d_in[3];
    const float* Wk2  = (const float*)d_in[4];
    const float* Wv1  = (const float*)d_in[5];
    const float* Wv2  = (const float*)d_in[6];
    const float* Wdot = (const float*)d_in[7];
    const int* esrc   = (const int*)d_in[8];
    const int* edst   = (const int*)d_in[9];
    float* out = (float*)d_out;

    k_hist<<<(N_EDGESC + 383) / 384, 384>>>(edst, Wq, Wdot, Wk2);  // 1
    k_scan<<<1, 1024>>>();                                         // 2
    k_scatter<<<(N_EDGESC + 255) / 256, 256>>>(esrc, edst);        // 3
    k_R<<<N_NODESC / RT_NODES, 384>>>(x);                          // 4 (profiled)
    k_passA<<<(N_EDGESC + 255) / 256, 256>>>(x, pos, Wk1, Wv1);    // 5
    k_passBout<<<(N_NODESC + BN - 1) / BN, 448>>>(Wv2, out);       // 6
}

// round 17
// speedup vs baseline: 1.3407x; 1.3407x over previous
#include <cuda_runtime.h>
#include <math.h>

#define N_NODESC 20000
#define N_EDGESC 120000
#define HY_STRIDE 44

// ---- static device scratch (zero-initialized at module load) ----
__device__ int   g_deg[N_NODESC];     // zero invariant restored by k_scatter each run
__device__ int   g_off[N_NODESC + 1];
__device__ int   g_cursor[N_NODESC];
__device__ int2  g_edge[N_EDGESC];               // sorted (src,dst)
__device__ float g_MW[16 * 384];                 // MW[p][t], t=j*24+u (computed in k_hist blk 0)
__device__ float g_R[(size_t)N_NODESC * 384];    // R[n][j*24+u]
__device__ float g_hy[(size_t)N_EDGESC * HY_STRIDE + 16]; // per SORTED slot: hv'[16], y[24], expv

#define C_EMB   8.4335730690754870f
#define C_V     0.05103103630798287f
#define C_LOGIT 0.003189439769248930f

__device__ __forceinline__ float susf(float v) {
    return (v > 0.f) ? __expf(-__fdividef(1.f, v)) : 0.f;
}
__device__ __forceinline__ float siluf(float z) {
    return __fdividef(z, 1.f + __expf(-z));
}

// ---------------- hist (+ block 0 computes MW once) ----------------
__global__ void k_hist(const int* __restrict__ dst, const float* __restrict__ Wq,
                       const float* __restrict__ Wdot, const float* __restrict__ Wk2) {
    int i = blockIdx.x * 384 + threadIdx.x;
    if (i < N_EDGESC) atomicAdd(&g_deg[dst[i]], 1);

    if (blockIdx.x == 0) {
        __shared__ float sM[16][17];
        int t = threadIdx.x;  // 0..383
        if (t < 256) {
            int p = t >> 4, w = t & 15;
            float a = 0.f;
            #pragma unroll
            for (int r = 0; r < 16; r++) a += __ldg(&Wq[p * 16 + r]) * __ldg(&Wdot[r * 16 + w]);
            sM[p][w] = a * 0.25f * C_LOGIT;
        }
        __syncthreads();
        int j = t / 24, u = t - j * 24;
        float wk[16];
        #pragma unroll
        for (int w = 0; w < 16; w++) wk[w] = __ldg(&Wk2[j * 384 + u * 16 + w]);
        #pragma unroll
        for (int p = 0; p < 16; p++) {
            float a = 0.f;
            #pragma unroll
            for (int w = 0; w < 16; w++) a += sM[p][w] * wk[w];
            g_MW[p * 384 + t] = a;
        }
    }
}

__global__ void k_scan() {
    __shared__ int s[1024];
    int tid = threadIdx.x;
    const int CH = (N_NODESC + 1023) / 1024;  // 20
    int base = tid * CH;
    int sum = 0;
    #pragma unroll
    for (int c = 0; c < CH; c++) {
        int idx = base + c;
        if (idx < N_NODESC) sum += g_deg[idx];
    }
    s[tid] = sum;
    __syncthreads();
    for (int d = 1; d < 1024; d <<= 1) {
        int v = (tid >= d) ? s[tid - d] : 0;
        __syncthreads();
        s[tid] += v;
        __syncthreads();
    }
    int run = s[tid] - sum;
    for (int c = 0; c < CH; c++) {
        int idx = base + c;
        if (idx < N_NODESC) {
            g_off[idx] = run;
            g_cursor[idx] = run;
            run += g_deg[idx];
        }
    }
    if (tid == 1023) g_off[N_NODESC] = s[1023];
}

// scatter + re-zero g_deg (restores zero invariant for the next graph replay)
__global__ void k_scatter(const int* __restrict__ src, const int* __restrict__ dst) {
    int i = blockIdx.x * blockDim.x + threadIdx.x;
    if (i < N_EDGESC) {
        int d = dst[i];
        int p = atomicAdd(&g_cursor[d], 1);
        g_edge[p] = make_int2(src[i], d);
        if (i < N_NODESC) g_deg[i] = 0;
    }
}

// ---------------- R GEMM: R[n][t] = sum_p x0[n][p]*MW[p][t] ----------------
#define RT_NODES 25
__global__ void k_R(const float* __restrict__ x) {
    __shared__ float sq[RT_NODES * 16];
    int t = threadIdx.x;  // 0..383

    float wr[16];
    #pragma unroll
    for (int p = 0; p < 16; p++) wr[p] = g_MW[p * 384 + t];   // coalesced, L2-hot

    int nb = blockIdx.x * RT_NODES;
    for (int i = t; i < RT_NODES * 16; i += 384) {
        int n = i >> 4, c = i & 15;
        sq[i] = x[(size_t)(nb + n) * 40 + c];
    }
    __syncthreads();

    float* Rp = g_R + (size_t)nb * 384 + t;
    #pragma unroll 5
    for (int n0 = 0; n0 < RT_NODES; n0++) {
        const float4* q4 = (const float4*)(sq + n0 * 16);
        float4 qa = q4[0], qb = q4[1], qc = q4[2], qd = q4[3];
        float s0 = wr[0] * qa.x;  float s1 = wr[1] * qa.y;
        float s2 = wr[2] * qa.z;  float s3 = wr[3] * qa.w;
        s0 += wr[4] * qb.x;  s1 += wr[5] * qb.y;
        s2 += wr[6] * qb.z;  s3 += wr[7] * qb.w;
        s0 += wr[8] * qc.x;  s1 += wr[9] * qc.y;
        s2 += wr[10] * qc.z; s3 += wr[11] * qc.w;
        s0 += wr[12] * qd.x; s1 += wr[13] * qd.y;
        s2 += wr[14] * qd.z; s3 += wr[15] * qd.w;
        Rp[(size_t)n0 * 384] = (s0 + s1) + (s2 + s3);
    }
}

// ---------------- pass A: register-dieted, __launch_bounds__(256,4) ----------------
__global__ void __launch_bounds__(256, 4)
k_passA(const float* __restrict__ x, const float* __restrict__ pos,
        const float* __restrict__ Wk1, const float* __restrict__ Wv1) {
    __shared__ float s_wkv[320];
    {
        int tt = threadIdx.x;
        if (tt < 160) { s_wkv[tt] = __ldg(&Wk1[tt]); s_wkv[160 + tt] = __ldg(&Wv1[tt]); }
    }
    __syncthreads();

    int i = blockIdx.x * blockDim.x + threadIdx.x;
    if (i >= N_EDGESC) return;
    int2 sd = g_edge[i];
    int s = sd.x, d = sd.y;
    float* row = g_hy + (size_t)i * HY_STRIDE;

    float ev0 = pos[s * 3 + 0] - pos[d * 3 + 0];
    float ev1 = pos[s * 3 + 1] - pos[d * 3 + 1];
    float ev2 = pos[s * 3 + 2] - pos[d * 3 + 2];
    float elen = sqrtf(ev0 * ev0 + ev1 * ev1 + ev2 * ev2 + 1e-12f);

    float wcut = susf(10.f * (1.f - elen * 0.25f));
    if (!(wcut > 0.f)) {
        float4 z4 = make_float4(0.f, 0.f, 0.f, 0.f);
        ((float4*)row)[0] = z4; ((float4*)row)[1] = z4;
        ((float4*)row)[2] = z4; ((float4*)row)[3] = z4;
        ((float4*)row)[10] = z4;
        return;
    }

    float tt = elen * 2.75f;
    int b0 = (int)tt;
    float d0 = tt - (float)b0;
    float g0 = (b0 >= 1 && b0 <= 10) ? (C_EMB * susf(d0 + 1.f) * susf(1.f - d0)) : 0.f;
    float g1 = (b0 >= 0 && b0 <= 9)  ? (C_EMB * susf(d0) * susf(2.f - d0)) : 0.f;
    int r0 = b0 - 1; if (r0 < 0) r0 = 0; if (r0 > 9) r0 = 9;
    int r1 = b0;     if (r1 < 0) r1 = 0; if (r1 > 9) r1 = 9;

    const float4* xp4 = (const float4*)(x + (size_t)s * 40);
    float y[24];
    float rinv = __frcp_rn(elen);

    {
        float4 a0 = __ldg(&xp4[0]), a1 = __ldg(&xp4[1]);
        float4 a2 = __ldg(&xp4[2]), a3 = __ldg(&xp4[3]);
        y[0] = a0.x;  y[1] = a0.y;  y[2] = a0.z;  y[3] = a0.w;
        y[4] = a1.x;  y[5] = a1.y;  y[6] = a1.z;  y[7] = a1.w;
        y[8] = a2.x;  y[9] = a2.y;  y[10] = a2.z; y[11] = a2.w;
        y[12] = a3.x; y[13] = a3.y; y[14] = a3.z; y[15] = a3.w;
    }
    {
        float4 b0v = __ldg(&xp4[4]);
        float4 b1v = __ldg(&xp4[5]);
        float4 b2v = __ldg(&xp4[6]);
        y[16] = (b0v.x * ev0 + b0v.y * ev1 + b0v.z * ev2) * rinv;
        y[17] = (b0v.w * ev0 + b1v.x * ev1 + b1v.y * ev2) * rinv;
        y[18] = (b1v.z * ev0 + b1v.w * ev1 + b2v.x * ev2) * rinv;
        y[19] = (b2v.y * ev0 + b2v.z * ev1 + b2v.w * ev2) * rinv;
    }
    {
        float4 b3v = __ldg(&xp4[7]);
        float4 b4v = __ldg(&xp4[8]);
        float4 b5v = __ldg(&xp4[9]);
        y[20] = (b3v.x * ev0 + b3v.y * ev1 + b3v.z * ev2) * rinv;
        y[21] = (b3v.w * ev0 + b4v.x * ev1 + b4v.y * ev2) * rinv;
        y[22] = (b4v.z * ev0 + b4v.w * ev1 + b5v.x * ev2) * rinv;
        y[23] = (b5v.y * ev0 + b5v.z * ev1 + b5v.w * ev2) * rinv;
    }

    float lg = 0.f;
    const float4* Rp = (const float4*)(g_R + (size_t)d * 384);
    #pragma unroll
    for (int j = 0; j < 16; j++) {
        float zk = g0 * s_wkv[r0 * 16 + j] + g1 * s_wkv[r1 * 16 + j];
        float hk = siluf(zk);
        float Sj = 0.f;
        #pragma unroll
        for (int q4 = 0; q4 < 6; q4++) {
            float4 r4 = __ldg(&Rp[j * 6 + q4]);
            Sj += r4.x * y[q4 * 4 + 0] + r4.y * y[q4 * 4 + 1]
                + r4.z * y[q4 * 4 + 2] + r4.w * y[q4 * 4 + 3];
        }
        lg += hk * Sj;
    }
    float expv = wcut * __expf(lg);
    float sev = sqrtf(expv);

    #pragma unroll
    for (int j4 = 0; j4 < 4; j4++) {
        float h0 = sev * siluf(g0 * s_wkv[160 + r0 * 16 + j4 * 4 + 0] + g1 * s_wkv[160 + r1 * 16 + j4 * 4 + 0]);
        float h1 = sev * siluf(g0 * s_wkv[160 + r0 * 16 + j4 * 4 + 1] + g1 * s_wkv[160 + r1 * 16 + j4 * 4 + 1]);
        float h2 = sev * siluf(g0 * s_wkv[160 + r0 * 16 + j4 * 4 + 2] + g1 * s_wkv[160 + r1 * 16 + j4 * 4 + 2]);
        float h3 = sev * siluf(g0 * s_wkv[160 + r0 * 16 + j4 * 4 + 3] + g1 * s_wkv[160 + r1 * 16 + j4 * 4 + 3]);
        ((float4*)row)[j4] = make_float4(h0, h1, h2, h3);
    }
    #pragma unroll
    for (int q4 = 0; q4 < 6; q4++)
        ((float4*)(row + 16))[q4] = make_float4(y[q4 * 4 + 0], y[q4 * 4 + 1],
                                                y[q4 * 4 + 2], y[q4 * 4 + 3]);
    ((float4*)row)[10] = make_float4(expv, 0.f, 0.f, 0.f);
}

// ---------------- fused pass B + output GEMM (scalar phase 2, split accumulators) ----------------
#define BN 28
__global__ void __launch_bounds__(448)
k_passBout(const float* __restrict__ Wv2, float* __restrict__ out) {
    __shared__ float sT[BN][384];     // 43,008 B
    __shared__ float sWt[32][34];     // [k_local][col], pad 2 (proven layout)

    int t = threadIdx.x;
    int l = t & 31, w = t >> 5;       // warp 0..13
    int base = blockIdx.x * BN;
    int par = l >> 4;
    int jj = l & 15;

    // ---- phase 1: passB (warp per node, 2 nodes/warp) ----
    #pragma unroll
    for (int q = 0; q < 2; q++) {
        int n = base + w * 2 + q;
        float acc[12];
        #pragma unroll
        for (int k = 0; k < 12; k++) acc[k] = 0.f;
        float z = 0.f;

        if (n < N_NODESC) {
            int beg = g_off[n], end = g_off[n + 1];
            if (beg < end) {
                const float* row = g_hy + (size_t)beg * HY_STRIDE;
                float A = row[l];
                float B = (l < 16) ? row[32 + l] : 0.f;
                for (int i = beg; i < end; i++) {
                    float A2 = 0.f, B2 = 0.f;
                    if (i + 1 < end) {
                        const float* row2 = g_hy + (size_t)(i + 1) * HY_STRIDE;
                        A2 = row2[l];
                        B2 = (l < 16) ? row2[32 + l] : 0.f;
                    }
                    z += __shfl_sync(0xffffffffu, B, 8);
                    float hval = __shfl_sync(0xffffffffu, A, jj);
                    #pragma unroll
                    for (int k = 0; k < 8; k++) {
                        float yv = __shfl_sync(0xffffffffu, A, 16 + par + 2 * k);
                        acc[k] += hval * yv;
                    }
                    #pragma unroll
                    for (int k = 8; k < 12; k++) {
                        float yv = __shfl_sync(0xffffffffu, B, par + 2 * k - 16);
                        acc[k] += hval * yv;
                    }
                    A = A2; B = B2;
                }
            }
        }
        if (z == 0.f) z = 1.f;
        float sc = rsqrtf(z);
        #pragma unroll
        for (int k = 0; k < 12; k++) sT[w * 2 + q][l + 32 * k] = acc[k] * sc;
    }
    __syncthreads();

    // ---- phase 2: GEMM out = C_V * sT @ W' (scalar LDS, 2-way split accumulators) ----
    float acc0a = 0.f, acc0b = 0.f, acc1a = 0.f, acc1b = 0.f;
    const float* r0 = sT[w * 2];
    const float* r1 = sT[w * 2 + 1];
    for (int kc = 0; kc < 12; kc++) {
        for (int i = t; i < 1024; i += 448) {
            int kk = i >> 5, col = i & 31;
            int k = kc * 32 + kk;
            sWt[kk][col] = __ldg(&Wv2[(k & 15) * 768 + (k >> 4) * 32 + col]);
        }
        __syncthreads();
        #pragma unroll 4
        for (int kk = 0; kk < 32; kk += 2) {
            float wv0 = sWt[kk][l];
            float wv1 = sWt[kk + 1][l];
            float t00 = r0[kc * 32 + kk];       // warp-broadcast
            float t01 = r0[kc * 32 + kk + 1];
            float t10 = r1[kc * 32 + kk];
            float t11 = r1[kc * 32 + kk + 1];
            acc0a += t00 * wv0;  acc0b += t01 * wv1;
            acc1a += t10 * wv0;  acc1b += t11 * wv1;
        }
        __syncthreads();
    }
    int n0 = base + w * 2, n1 = n0 + 1;
    if (n0 < N_NODESC) out[n0 * 32 + l] = (acc0a + acc0b) * C_V;
    if (n1 < N_NODESC) out[n1 * 32 + l] = (acc1a + acc1b) * C_V;
}

// ---------------- launch: single stream, 6 kernels ----------------
extern "C" void kernel_launch(void* const* d_in, const int* in_sizes, int n_in,
                              void* d_out, int out_size) {
    (void)in_sizes; (void)n_in; (void)out_size;
    const float* x    = (const float*)d_in[0];
    const float* pos  = (const float*)d_in[1];
    const float* Wq   = (const float*)d_in[2];
    const float* Wk1  = (const float*)d_in[3];
    const float* Wk2  = (const float*)d_in[4];
    const float* Wv1  = (const float*)d_in[5];
    const float* Wv2  = (const float*)d_in[6];
    const float* Wdot = (const float*)d_in[7];
    const int* esrc   = (const int*)d_in[8];
    const int* edst   = (const int*)d_in[9];
    float* out = (float*)d_out;

    k_hist<<<(N_EDGESC + 383) / 384, 384>>>(edst, Wq, Wdot, Wk2);  // 1
    k_scan<<<1, 1024>>>();                                         // 2
    k_scatter<<<(N_EDGESC + 255) / 256, 256>>>(esrc, edst);        // 3
    k_R<<<N_NODESC / RT_NODES, 384>>>(x);                          // 4 (profiled)
    k_passA<<<(N_EDGESC + 255) / 256, 256>>>(x, pos, Wk1, Wv1);    // 5
    k_passBout<<<(N_NODESC + BN - 1) / BN, 448>>>(Wv2, out);       // 6
}